// round 14
// baseline (speedup 1.0000x reference)
#include <cuda_runtime.h>
#include <cuda_bf16.h>
#include <cstdint>

// ---------------------------------------------------------------------------
// GIFNeuron fused: h = x @ W^T + b  then per-(b,h) GIF scan over T=2048.
// Single launch: 32 scan CTAs (wave-1 resident) + 1024 GEMM CTAs in
// t-block-major order. GEMM tiles publish per-(b,tblock) counters with
// release atomics; scan CTAs acquire-poll them and trail by one t-block,
// hiding the ~110us scan under the ~415us issue-floor GEMM.
// Counters are SELF-RESETTING (second consumer swaps back to 0): every
// invocation starts and ends with counters at 0 -> graph-replay safe with
// no host-side reset.
// GEMM body: verbatim round-1 (bit-exact vs reference).
// Scan body: verbatim round-3 fast-path + exact-redo (best measured).
// Outputs flattened: spikes [B,T,H] | v_f [B,H] | theta_f [B,H]
// ---------------------------------------------------------------------------

#define M_DIM 32768   // B*T
#define N_DIM 512     // H
#define K_DIM 512     // IN
#define B_DIM 16
#define T_DIM 2048

#define NSCAN_BLK 32          // scan CTAs (blockIdx 0..31)
#define NGEMM_BLK 1024        // GEMM tiles
#define NMB 256               // m-blocks (16 b x 16 t-blocks)

__device__ float g_h[(size_t)M_DIM * N_DIM];   // 64 MB scratch
__device__ int   g_cnt[NMB];                   // per-m-block counters (always 0 at entry/exit)

#define BM 128
#define BN 128
#define BK 16
#define TM 8
#define TN 8

__device__ __forceinline__ void publish_release(int* p) {
    int old;
    asm volatile("atom.global.add.release.gpu.s32 %0, [%1], 1;"
                 : "=r"(old) : "l"(p) : "memory");
}

__device__ __forceinline__ int load_acquire(const int* p) {
    int v;
    asm volatile("ld.global.acquire.gpu.b32 %0, [%1];"
                 : "=r"(v) : "l"(p) : "memory");
    return v;
}

__device__ __forceinline__ int consume_mark(int* p) {
    int old;
    asm volatile("atom.global.add.acq_rel.gpu.s32 %0, [%1], 1;"
                 : "=r"(old) : "l"(p) : "memory");
    return old;
}

__global__ __launch_bounds__(256, 2)
void fused_kernel(const float* __restrict__ A,
                  const float* __restrict__ Bw,
                  const float* __restrict__ bias,
                  float* __restrict__ spikes,
                  float* __restrict__ v_out,
                  float* __restrict__ theta_out)
{
    __shared__ float As[BK][BM];
    __shared__ float Bs[BK][BN];

    const int tid = threadIdx.x;

    if (blockIdx.x >= NSCAN_BLK) {
        // ================= GEMM tile (verbatim round-1 body) =================
        const int g  = blockIdx.x - NSCAN_BLK;       // 0..1023
        const int tb = g >> 6;                       // t-block 0..15 (major)
        const int bb = (g >> 2) & 15;                // batch 0..15
        const int nn = g & 3;                        // n-tile 0..3
        const int mb = bb * 16 + tb;                 // m-block index
        const int bm = mb * BM;
        const int bn = nn * BN;

        const int tr = (tid >> 4) * TM;
        const int tc = (tid & 15) * TN;

        float acc[TM][TN];
#pragma unroll
        for (int i = 0; i < TM; i++)
#pragma unroll
            for (int j = 0; j < TN; j++)
                acc[i][j] = 0.0f;

        const float* Ab = A  + (size_t)bm * K_DIM;
        const float* Bb = Bw + (size_t)bn * K_DIM;

        for (int k0 = 0; k0 < K_DIM; k0 += BK) {
#pragma unroll
            for (int i = 0; i < 2; i++) {
                int idx = tid + i * 256;
                int row = idx >> 2;
                int kq  = (idx & 3) << 2;
                float4 av = *(const float4*)(Ab + (size_t)row * K_DIM + k0 + kq);
                As[kq + 0][row] = av.x;
                As[kq + 1][row] = av.y;
                As[kq + 2][row] = av.z;
                As[kq + 3][row] = av.w;
                float4 bv = *(const float4*)(Bb + (size_t)row * K_DIM + k0 + kq);
                Bs[kq + 0][row] = bv.x;
                Bs[kq + 1][row] = bv.y;
                Bs[kq + 2][row] = bv.z;
                Bs[kq + 3][row] = bv.w;
            }
            __syncthreads();

#pragma unroll
            for (int kk = 0; kk < BK; kk++) {
                float ar[TM], br[TN];
#pragma unroll
                for (int i = 0; i < TM; i++) ar[i] = As[kk][tr + i];
#pragma unroll
                for (int j = 0; j < TN; j++) br[j] = Bs[kk][tc + j];
#pragma unroll
                for (int i = 0; i < TM; i++)
#pragma unroll
                    for (int j = 0; j < TN; j++)
                        acc[i][j] = fmaf(ar[i], br[j], acc[i][j]);
            }
            __syncthreads();
        }

#pragma unroll
        for (int i = 0; i < TM; i++) {
            size_t crow = (size_t)(bm + tr + i) * N_DIM + bn + tc;
#pragma unroll
            for (int j = 0; j < TN; j += 4) {
                float4 o;
                o.x = acc[i][j + 0] + bias[bn + tc + j + 0];
                o.y = acc[i][j + 1] + bias[bn + tc + j + 1];
                o.z = acc[i][j + 2] + bias[bn + tc + j + 2];
                o.w = acc[i][j + 3] + bias[bn + tc + j + 3];
                *(float4*)(g_h + crow + j) = o;
            }
        }

        __syncthreads();
        if (tid == 0) {
            __threadfence();                 // order this thread's (and CTA's) h stores
            publish_release(&g_cnt[mb]);     // release-add: publishes tile
        }
        return;
    }

    // ================= Scan CTA (round-3 body + acquire waits) =================
    const int idx = blockIdx.x * 256 + tid;          // 0..8191
    const int b   = idx >> 9;                        // == blockIdx.x >> 1
    const int hh  = idx & 511;

    const float* hp = g_h    + (size_t)b * T_DIM * N_DIM + hh;
    float*       sp = spikes + (size_t)b * T_DIM * N_DIM + hh;

    const float DECAY = 0.90483741803595952f;   // exp(-1/10)
    const float MAGIC = 12582912.0f;            // 2^23 + 2^22

    float v = 0.0f;
    float theta = 1.0f;
    float r = 1.0f;

    for (int tb = 0; tb < 16; tb++) {
        int* cp = &g_cnt[b * 16 + tb];
        // Acquire-poll: all 4 n-tiles of m-block (b, tb) published.
        if (tid == 0) {
            while (load_acquire(cp) < 4) { }
        }
        __syncthreads();
        __threadfence();                             // propagate visibility CTA-wide

        const int tbase = tb * 128;
        float cur[16];
#pragma unroll
        for (int u = 0; u < 16; u++)
            cur[u] = hp[(size_t)(tbase + u) * N_DIM];

        for (int blk = 0; blk < 8; blk++) {
            const int t0 = tbase + blk * 16;
            float nxt[16];
            if (blk < 7) {
#pragma unroll
                for (int u = 0; u < 16; u++)
                    nxt[u] = hp[(size_t)(t0 + 16 + u) * N_DIM];
            } else {
#pragma unroll
                for (int u = 0; u < 16; u++)
                    nxt[u] = 0.0f;
            }

            const float v_save  = v;
            const float th_save = theta;
            float out[16];
            int flag = 0;

#pragma unroll
            for (int u = 0; u < 16; u++) {
                v = fmaf(v, DECAY, cur[u]);
                float cl = 32.0f * theta;
                flag |= (fabsf(v) > cl);                   // clamp engages -> redo
                float qm = fmaf(v, r, -0.499999f);
                float t1 = __fadd_rn(qm, MAGIC);
                float s0 = __fsub_rn(t1, MAGIC);           // ~floor(v/theta)
                flag |= (s0 > 16.0f);                      // clip engages -> redo
                float s = fmaxf(s0, 0.0f);
                float d = fmaf(-s, theta, v);              // exact residual
                flag |= ((d < 0.0f) & (s > 0.0f));         // s too big
                flag |= (d >= theta * 0.99999905f);        // s too small / RN boundary
                v = d;
                theta = theta + 0.01f * s - 0.01f * (theta - 1.0f);
                asm("rcp.approx.f32 %0, %1;" : "=f"(r) : "f"(theta));
                out[u] = s;
            }

            if (__builtin_expect(flag, 0)) {
                // exact reference-semantics redo (bit-identical slow path)
                v = v_save;
                theta = th_save;
#pragma unroll
                for (int u = 0; u < 16; u++) {
                    v = fmaf(v, DECAY, cur[u]);
                    float cl = 32.0f * theta;
                    v = fminf(fmaxf(v, -cl), cl);
                    float s = floorf(v / theta);
                    s = fminf(fmaxf(s, 0.0f), 16.0f);
                    v = fmaf(-s, theta, v);
                    theta = theta + 0.01f * s - 0.01f * (theta - 1.0f);
                    out[u] = s;
                }
                asm("rcp.approx.f32 %0, %1;" : "=f"(r) : "f"(theta));
            }

#pragma unroll
            for (int u = 0; u < 16; u++)
                sp[(size_t)(t0 + u) * N_DIM] = out[u];

#pragma unroll
            for (int u = 0; u < 16; u++)
                cur[u] = nxt[u];
        }

        // Self-resetting consume: counter 4 -> 5 -> 6; 2nd consumer resets to 0.
        // Both watchers have already passed their wait, and no GEMM CTA of this
        // launch will touch it again -> next invocation starts from 0.
        if (tid == 0) {
            int old = consume_mark(cp);
            if (old == 5) {
                int dummy;
                asm volatile("atom.global.exch.b32 %0, [%1], 0;"
                             : "=r"(dummy) : "l"(cp) : "memory");
            }
        }
    }

    v_out[idx]     = v;
    theta_out[idx] = theta;
}

// ---------------------------------------------------------------------------
// kernel_launch
// Inputs (metadata order): x [16,2048,512] f32, W [512,512] f32, b [512] f32
// Output: float32, spikes | v_f | theta_f
// ---------------------------------------------------------------------------
extern "C" void kernel_launch(void* const* d_in, const int* in_sizes, int n_in,
                              void* d_out, int out_size)
{
    const float* x = (const float*)d_in[0];
    const float* W = (const float*)d_in[1];
    const float* b = (const float*)d_in[2];

    float* out    = (float*)d_out;
    float* spikes = out;
    float* v_f    = out + (size_t)B_DIM * T_DIM * N_DIM;
    float* th_f   = v_f + (size_t)B_DIM * N_DIM;

    fused_kernel<<<NSCAN_BLK + NGEMM_BLK, 256>>>(x, W, b, spikes, v_f, th_f);
}